// round 4
// baseline (speedup 1.0000x reference)
#include <cuda_runtime.h>
#include <utility>

// =====================================================================
// HiPPO-LegS reconstruction via scaled Clenshaw backward recurrence,
// vectorized with sm_103a packed fp32 FMA (fma.rn.f32x2): each step is
//   tt = fma2(b2, beta2, c2)     (beta2/c2 broadcast from smem)
//   b1 = fma2(o1, x2, tt)        (x2 per-thread register)
// 8 FFMA2 per step per warp (V=8 elems -> 4 lanespairs), 16 pipe cycles.
// Power-of-two rescale steps select a pre-scaled x register (free).
// Grid: 1024 blocks of 64 threads for ~1% SM load imbalance.
// =====================================================================

#define NDEG 256
#define V    8
#define VP   (V / 2)
#define TPB  64

// ---------------- compile-time scaling machinery ----------------

__host__ __device__ constexpr double c_TH()  { return 9.5367431640625e-07; } // 2^-20
__host__ __device__ constexpr double c_RHO() { return 1048576.0; }           // 2^20

__host__ __device__ constexpr double Ak(int k) { return (2.0 * k + 1.0) / (double)(k + 1); }
__host__ __device__ constexpr double Bk(int k) { return (double)k / (double)(k + 1); }

__host__ __device__ constexpr double s_of(int k) {
    if (k >= NDEG + 1) return 1.0;
    double s = 1.0;
    for (int j = NDEG; j >= k; --j) {
        s /= Ak(j);
        if (s < c_TH()) s *= c_RHO();
    }
    return s;
}

__host__ __device__ constexpr bool boosted(int k) {
    if (k >= NDEG + 1) return false;
    double s = 1.0;
    for (int j = NDEG; j >= k; --j) {
        s /= Ak(j);
        if (s < c_TH()) {
            s *= c_RHO();
            if (j == k) return true;
        }
    }
    return false;
}

__host__ __device__ constexpr double beta_of(int k) {
    return Bk(k + 1) * s_of(k) / s_of(k + 2);
}

__host__ __device__ constexpr double csqrt(double v) {
    double g = v < 1.0 ? 1.0 : v;
    for (int i = 0; i < 100; ++i) g = 0.5 * (g + v / g);
    return g;
}

__host__ __device__ constexpr float g_of(int k) {
    return (float)(s_of(k) * csqrt(2.0 * k + 1.0));
}

struct FTab { float v[NDEG + 1]; };
template <size_t... I>
constexpr FTab make_gtab(std::index_sequence<I...>) {
    return FTab{{ (I == 0 ? 0.0f : g_of((int)I))... }};
}
template <size_t... I>
constexpr FTab make_btab(std::index_sequence<I...>) {
    return FTab{{ ((float)(-beta_of((int)I)))... }};
}
__constant__ FTab G = make_gtab(std::make_index_sequence<NDEG + 1>{});
__constant__ FTab B = make_btab(std::make_index_sequence<NDEG + 1>{});

// ---------------- f32x2 helpers ----------------

typedef unsigned long long u64;

__device__ __forceinline__ u64 pack2(float lo, float hi) {
    u64 r;
    asm("mov.b64 %0, {%1, %2};" : "=l"(r) : "f"(lo), "f"(hi));
    return r;
}
__device__ __forceinline__ void unpack2(u64 v, float& lo, float& hi) {
    asm("mov.b64 {%0, %1}, %2;" : "=f"(lo), "=f"(hi) : "l"(v));
}
__device__ __forceinline__ u64 fma2(u64 a, u64 b, u64 c) {
    u64 d;
    asm("fma.rn.f32x2 %0, %1, %2, %3;" : "=l"(d) : "l"(a), "l"(b), "l"(c));
    return d;
}

// ---------------- Clenshaw steps, chunked template expansion ----------------
// Invariant entering step K: b1[p] = s_{K+1}*b_{K+1}, b2[p] = s_{K+2}*b_{K+2}

template <int K>
__device__ __forceinline__ void one_step(const u64* __restrict__ sb,
                                         const u64* __restrict__ scc,
                                         const u64 (&x2)[VP], const u64 (&xr2)[VP],
                                         u64 (&b1)[VP], u64 (&b2)[VP]) {
    constexpr bool BOOST = boosted(K);
    const u64 beta2 = sb[K];    // LDS.64 broadcast
    const u64 c2    = scc[K];   // LDS.64 broadcast
#pragma unroll
    for (int p = 0; p < VP; ++p) {
        u64 o1 = b1[p];
        u64 tt = fma2(b2[p], beta2, c2);               // packed FFMA
        b1[p]  = fma2(o1, BOOST ? xr2[p] : x2[p], tt); // packed FFMA
        b2[p]  = o1;                                   // rename (free, unrolled)
    }
}

template <int K, size_t... J>
__device__ __forceinline__ void chunk_steps(std::index_sequence<J...>,
                                            const u64* __restrict__ sb,
                                            const u64* __restrict__ scc,
                                            const u64 (&x2)[VP], const u64 (&xr2)[VP],
                                            u64 (&b1)[VP], u64 (&b2)[VP]) {
    (one_step<K - (int)J>(sb, scc, x2, xr2, b1, b2), ...);
}

template <int K>
struct Step {
    static constexpr int CH = (K + 1 < 16) ? (K + 1) : 16;
    static __device__ __forceinline__ void run(const u64* __restrict__ sb,
                                               const u64* __restrict__ scc,
                                               const u64 (&x2)[VP], const u64 (&xr2)[VP],
                                               u64 (&b1)[VP], u64 (&b2)[VP]) {
        chunk_steps<K>(std::make_index_sequence<CH>{}, sb, scc, x2, xr2, b1, b2);
        Step<K - CH>::run(sb, scc, x2, xr2, b1, b2);
    }
};
template <>
struct Step<-1> {
    static __device__ __forceinline__ void run(const u64* __restrict__,
                                               const u64* __restrict__,
                                               const u64 (&)[VP], const u64 (&)[VP],
                                               u64 (&)[VP], u64 (&)[VP]) {}
};

// ---------------- kernel ----------------

__global__ __launch_bounds__(TPB, 8) void hippo_clenshaw_kernel(
    const float* __restrict__ t, const float* __restrict__ coef,
    const int* __restrict__ ctp, float* __restrict__ out, int n)
{
    __shared__ u64 sb[NDEG + 1];   // packed {-beta_k, -beta_k}
    __shared__ u64 scc[NDEG + 1];  // packed {c_k, c_k},  c_k = g_k * coef[k-1]
    for (int i = threadIdx.x; i <= NDEG; i += TPB) {
        float bk = B.v[i];
        float ck = (i == 0) ? 0.0f : G.v[i] * __ldg(coef + i - 1);
        sb[i]  = pack2(bk, bk);
        scc[i] = pack2(ck, ck);
    }
    __syncthreads();

    // curr_t: tolerate int32 payload (expected) or a float bit pattern
    float ct = 1.0f;
    if (ctp) {
        int iv   = *ctp;
        float fv = __int_as_float(iv);
        ct = (iv > 0 && iv < (1 << 20)) ? (float)iv : fv;
    }
    const float sc2 = 2.0f / ct;

    const long long base = ((long long)blockIdx.x * TPB + threadIdx.x) * V;
    if (base >= n) return;

    constexpr float INVS0 = (float)(1.0 / s_of(0));
    constexpr float RHOF  = (float)c_RHO();

    float xv[V];
    if (base + V <= n) {
        float4 ta = *reinterpret_cast<const float4*>(t + base);
        float4 tb = *reinterpret_cast<const float4*>(t + base + 4);
        xv[0] = ta.x; xv[1] = ta.y; xv[2] = ta.z; xv[3] = ta.w;
        xv[4] = tb.x; xv[5] = tb.y; xv[6] = tb.z; xv[7] = tb.w;
    } else {
#pragma unroll
        for (int v = 0; v < V; ++v) {
            long long idx = base + v;
            xv[v] = (idx < n) ? t[idx] : 0.0f;
        }
    }

    u64 x2[VP], xr2[VP], b1[VP], b2[VP];
#pragma unroll
    for (int p = 0; p < VP; ++p) {
        float xa = fmaf(xv[2 * p],     sc2, -1.0f);
        float xb = fmaf(xv[2 * p + 1], sc2, -1.0f);
        x2[p]  = pack2(xa, xb);
        xr2[p] = pack2(xa * RHOF, xb * RHOF);  // exact pow2 scale
        b1[p]  = 0;
        b2[p]  = 0;
    }

    Step<NDEG>::run(sb, scc, x2, xr2, b1, b2);

    float r[V];
#pragma unroll
    for (int p = 0; p < VP; ++p) {
        float lo, hi;
        unpack2(b1[p], lo, hi);
        r[2 * p]     = lo * INVS0;
        r[2 * p + 1] = hi * INVS0;
    }

    if (base + V <= n) {
        *reinterpret_cast<float4*>(out + base) =
            make_float4(r[0], r[1], r[2], r[3]);
        *reinterpret_cast<float4*>(out + base + 4) =
            make_float4(r[4], r[5], r[6], r[7]);
    } else {
#pragma unroll
        for (int v = 0; v < V; ++v) {
            long long idx = base + v;
            if (idx < n) out[idx] = r[v];
        }
    }
}

// ---------------- launch ----------------

extern "C" void kernel_launch(void* const* d_in, const int* in_sizes, int n_in,
                              void* d_out, int out_size)
{
    // Identify inputs by size: big -> t, 1 -> curr_t, remaining -> coef
    int ti = -1, ci = -1, si = -1;
    for (int i = 0; i < n_in; ++i) {
        if (in_sizes[i] == out_size && ti < 0)      ti = i;
        else if (in_sizes[i] == 1 && si < 0)        si = i;
        else if (ci < 0)                            ci = i;
    }
    if (ti < 0) ti = 0;
    if (ci < 0) ci = (n_in > 1 ? 1 : 0);

    const float* t    = (const float*)d_in[ti];
    const float* coef = (const float*)d_in[ci];
    const int*   ct   = (si >= 0) ? (const int*)d_in[si] : nullptr;

    int n = out_size;
    int elems_per_block = TPB * V;
    int blocks = (n + elems_per_block - 1) / elems_per_block;
    hippo_clenshaw_kernel<<<blocks, TPB>>>(t, coef, ct, (float*)d_out, n);
}

// round 5
// speedup vs baseline: 1.2201x; 1.2201x over previous
#include <cuda_runtime.h>
#include <utility>

// =====================================================================
// HiPPO-LegS reconstruction:  out = sum_{k=1..256} coef[k-1]*sqrt(2k+1)*P_k(x)
// x = 2*t/curr_t - 1, 524288 points.
//
// Scaled Clenshaw backward recurrence, compile-time constants:
//   tt = FFMA(b2, -beta_imm, c)   (imm form, rt_SMSP=1)
//   b1 = FFMA(b1, x, tt)          (reg form, rt_SMSP=2)
// V=4 elems/thread, TPB=128 -> 4096 warps (6.9/SMSP) to hide FFMA+LDS
// latency (R4 lesson: we are stall-bound, not issue-bound).
// =====================================================================

#define NDEG 256
#define V    4
#define TPB  128

// ---------------- compile-time scaling machinery ----------------

__host__ __device__ constexpr double c_TH()  { return 9.5367431640625e-07; } // 2^-20
__host__ __device__ constexpr double c_RHO() { return 1048576.0; }           // 2^20

__host__ __device__ constexpr double Ak(int k) { return (2.0 * k + 1.0) / (double)(k + 1); }
__host__ __device__ constexpr double Bk(int k) { return (double)k / (double)(k + 1); }

__host__ __device__ constexpr double s_of(int k) {
    if (k >= NDEG + 1) return 1.0;
    double s = 1.0;
    for (int j = NDEG; j >= k; --j) {
        s /= Ak(j);
        if (s < c_TH()) s *= c_RHO();
    }
    return s;
}

__host__ __device__ constexpr bool boosted(int k) {
    if (k >= NDEG + 1) return false;
    double s = 1.0;
    for (int j = NDEG; j >= k; --j) {
        s /= Ak(j);
        if (s < c_TH()) {
            s *= c_RHO();
            if (j == k) return true;
        }
    }
    return false;
}

__host__ __device__ constexpr double beta_of(int k) {
    return Bk(k + 1) * s_of(k) / s_of(k + 2);
}

__host__ __device__ constexpr double csqrt(double v) {
    double g = v < 1.0 ? 1.0 : v;
    for (int i = 0; i < 100; ++i) g = 0.5 * (g + v / g);
    return g;
}

__host__ __device__ constexpr float g_of(int k) {
    return (float)(s_of(k) * csqrt(2.0 * k + 1.0));
}

struct GTab { float v[NDEG + 1]; };
template <size_t... I>
constexpr GTab make_gtab(std::index_sequence<I...>) {
    return GTab{{ (I == 0 ? 0.0f : g_of((int)I))... }};
}
__constant__ GTab G = make_gtab(std::make_index_sequence<NDEG + 1>{});

// ---------------- Clenshaw steps, chunked template expansion ----------------
// Invariant entering step K: b1[v] = s_{K+1}*b_{K+1}, b2[v] = s_{K+2}*b_{K+2}

template <int K>
__device__ __forceinline__ void one_step(const float* __restrict__ sc,
                                         const float (&x)[V], const float (&xr)[V],
                                         float (&b1)[V], float (&b2)[V]) {
    constexpr float BETA  = (float)(-beta_of(K));  // immediate multiplier
    constexpr bool  BOOST = boosted(K);
    const float c = sc[K];                          // LDS broadcast
#pragma unroll
    for (int v = 0; v < V; ++v) {
        float o1 = b1[v];
        float tt = fmaf(b2[v], BETA, c);            // FFMA imm  (rt=1)
        b1[v]    = fmaf(o1, BOOST ? xr[v] : x[v], tt); // FFMA reg (rt=2)
        b2[v]    = o1;                              // rename (free when unrolled)
    }
}

template <int K, size_t... J>
__device__ __forceinline__ void chunk_steps(std::index_sequence<J...>,
                                            const float* __restrict__ sc,
                                            const float (&x)[V], const float (&xr)[V],
                                            float (&b1)[V], float (&b2)[V]) {
    (one_step<K - (int)J>(sc, x, xr, b1, b2), ...);
}

template <int K>
struct Step {
    static constexpr int CH = (K + 1 < 16) ? (K + 1) : 16;
    static __device__ __forceinline__ void run(const float* __restrict__ sc,
                                               const float (&x)[V], const float (&xr)[V],
                                               float (&b1)[V], float (&b2)[V]) {
        chunk_steps<K>(std::make_index_sequence<CH>{}, sc, x, xr, b1, b2);
        Step<K - CH>::run(sc, x, xr, b1, b2);
    }
};
template <>
struct Step<-1> {
    static __device__ __forceinline__ void run(const float* __restrict__,
                                               const float (&)[V], const float (&)[V],
                                               float (&)[V], float (&)[V]) {}
};

// ---------------- kernel ----------------

__global__ __launch_bounds__(TPB) void hippo_clenshaw_kernel(
    const float* __restrict__ t, const float* __restrict__ coef,
    const int* __restrict__ ctp, float* __restrict__ out, int n)
{
    __shared__ float sc[NDEG + 1];
    for (int i = threadIdx.x; i <= NDEG; i += TPB)
        sc[i] = (i == 0) ? 0.0f : G.v[i] * __ldg(coef + i - 1);
    __syncthreads();

    // curr_t: tolerate int32 payload (expected) or a float bit pattern
    float ct = 1.0f;
    if (ctp) {
        int iv   = *ctp;
        float fv = __int_as_float(iv);
        ct = (iv > 0 && iv < (1 << 20)) ? (float)iv : fv;
    }
    const float sc2 = 2.0f / ct;

    const long long base = ((long long)blockIdx.x * TPB + threadIdx.x) * V;
    if (base >= n) return;

    constexpr float INVS0 = (float)(1.0 / s_of(0));
    constexpr float RHOF  = (float)c_RHO();

    float tv[V];
    if (base + V <= n) {
        float4 ta = *reinterpret_cast<const float4*>(t + base);
        tv[0] = ta.x; tv[1] = ta.y; tv[2] = ta.z; tv[3] = ta.w;
    } else {
#pragma unroll
        for (int v = 0; v < V; ++v) {
            long long idx = base + v;
            tv[v] = (idx < n) ? t[idx] : 0.0f;
        }
    }

    float x[V], xr[V], b1[V], b2[V];
#pragma unroll
    for (int v = 0; v < V; ++v) {
        x[v]  = fmaf(tv[v], sc2, -1.0f);
        xr[v] = x[v] * RHOF;   // exact pow2 pre-scale for boost steps
        b1[v] = 0.0f;
        b2[v] = 0.0f;
    }

    Step<NDEG>::run(sc, x, xr, b1, b2);

    if (base + V <= n) {
        *reinterpret_cast<float4*>(out + base) =
            make_float4(b1[0] * INVS0, b1[1] * INVS0,
                        b1[2] * INVS0, b1[3] * INVS0);
    } else {
#pragma unroll
        for (int v = 0; v < V; ++v) {
            long long idx = base + v;
            if (idx < n) out[idx] = b1[v] * INVS0;
        }
    }
}

// ---------------- launch ----------------

extern "C" void kernel_launch(void* const* d_in, const int* in_sizes, int n_in,
                              void* d_out, int out_size)
{
    // Identify inputs by size: big -> t, 1 -> curr_t, remaining -> coef
    int ti = -1, ci = -1, si = -1;
    for (int i = 0; i < n_in; ++i) {
        if (in_sizes[i] == out_size && ti < 0)      ti = i;
        else if (in_sizes[i] == 1 && si < 0)        si = i;
        else if (ci < 0)                            ci = i;
    }
    if (ti < 0) ti = 0;
    if (ci < 0) ci = (n_in > 1 ? 1 : 0);

    const float* t    = (const float*)d_in[ti];
    const float* coef = (const float*)d_in[ci];
    const int*   ct   = (si >= 0) ? (const int*)d_in[si] : nullptr;

    int n = out_size;
    int elems_per_block = TPB * V;
    int blocks = (n + elems_per_block - 1) / elems_per_block;
    hippo_clenshaw_kernel<<<blocks, TPB>>>(t, coef, ct, (float*)d_out, n);
}